// round 2
// baseline (speedup 1.0000x reference)
#include <cuda_runtime.h>

#define S 2048
#define B 64
#define H 8
#define KK 12
#define NPOS 11
#define TBL 4096  // 1<<KK

// Scratch (__device__ globals; no allocations allowed).
__device__ uint4 g_AQ4[S];              // per s: 8 x u16 = (h<<12) + addr_q  (disjoint bits -> sum fits)
__device__ uint4 g_AK4[S];              // per s: 8 x u16 = addr_k
__device__ uint4 g_AP4[S];              // per rel: 8 x u16 = addr_p
__device__ uint4 g_tb4[H * TBL / 16];   // head_table as bytes, [h][addr]
__device__ float g_values[S * B];       // values[s][b] = table_v[b][addr_v(s,b)]

// ---------------------------------------------------------------------------
// Fused prep: byte table, per-(s,h) partial addresses, and values gather.
// Grid covers S*B = 131072 threads. Token bits read directly (rows L1-hot).
__global__ void __launch_bounds__(256) k_prep(
        const int* __restrict__ tokens,
        const int* __restrict__ conn_heads,
        const float* __restrict__ head_table,
        const int* __restrict__ conn_v,
        const float* __restrict__ table_v) {
    int i = blockIdx.x * blockDim.x + threadIdx.x;

    if (i < H * TBL)
        ((unsigned char*)g_tb4)[i] = (head_table[i] != 0.0f) ? 1 : 0;

    if (i < S * H) {
        int s = i >> 3, h = i & 7;
        int aq = 0, ak = 0, ap = 0;
#pragma unroll
        for (int j = 0; j < KK; j++) {
            int c = __ldg(&conn_heads[h * KK + j]);
            int p2 = 1 << (KK - 1 - j);
            if (c < B)          aq += (__ldg(&tokens[s * B + c]) != 0) * p2;
            else if (c < 2 * B) ak += (__ldg(&tokens[s * B + (c - B)]) != 0) * p2;
            else                ap += ((s >> (NPOS - 1 - (c - 2 * B))) & 1) * p2;
        }
        ((unsigned short*)g_AQ4)[i] = (unsigned short)((h << 12) + aq);
        ((unsigned short*)g_AK4)[i] = (unsigned short)ak;
        ((unsigned short*)g_AP4)[i] = (unsigned short)ap;
    }

    {   // values: all S*B threads
        int s = i >> 6, b = i & 63;
        int addr = 0;
#pragma unroll
        for (int j = 0; j < KK; j++) {
            int c = __ldg(&conn_v[b * KK + j]);
            addr += (__ldg(&tokens[s * B + c]) != 0) << (KK - 1 - j);
        }
        g_values[i] = __ldg(&table_v[b * TBL + addr]);
    }
}

// ---------------------------------------------------------------------------
// Main: one WARP per query row q, 8 rows per 256-thread block (table staged
// once per block). Warp scans k ascending in 32-wide chunks with prefetch of
// the next chunk; in-warp ballot early-exit when any vote hits H (the global
// max). Argmax with first-index tie-break via enc = (v<<11)|(2047-k).
__global__ void __launch_bounds__(256) k_main(float* __restrict__ out) {
    __shared__ unsigned char s_tb[H * TBL];   // 32 KB byte table

    int tid = threadIdx.x;
    uint4* st4 = (uint4*)s_tb;
#pragma unroll
    for (int i = 0; i < 8; i++) st4[tid + i * 256] = g_tb4[tid + i * 256];
    __syncthreads();

    int warp = tid >> 5, lane = tid & 31;
    int q = blockIdx.x * 8 + warp;

    uint4 aq = g_AQ4[q];
    int niter = (q >> 5) + 1;

    int k = lane;
    int kc = min(k, q);
    uint4 ak = __ldg(&g_AK4[kc]);
    uint4 ap = __ldg(&g_AP4[q - kc]);

    int best = -1;
    for (int it = 0; it < niter; it++) {
        uint4 cak = ak, cap = ap;
        int kcur = k;
        k += 32;
        if (it + 1 < niter) {          // warp-uniform predicate
            int kn = min(k, q);
            ak = __ldg(&g_AK4[kn]);
            ap = __ldg(&g_AP4[q - kn]);
        }
        // packed u16 adds: (h<<12) + (aq+ak+ap) <= 32767 per lane, no carry.
        unsigned wx = cak.x + cap.x + aq.x;
        unsigned wy = cak.y + cap.y + aq.y;
        unsigned wz = cak.z + cap.z + aq.z;
        unsigned ww = cak.w + cap.w + aq.w;
        int v = s_tb[wx & 0xFFFF] + s_tb[wx >> 16]
              + s_tb[wy & 0xFFFF] + s_tb[wy >> 16]
              + s_tb[wz & 0xFFFF] + s_tb[wz >> 16]
              + s_tb[ww & 0xFFFF] + s_tb[ww >> 16];
        bool valid = (kcur <= q);
        if (valid) best = max(best, (v << 11) | (2047 - kcur));
        // First chunk containing the maximum possible vote (H) holds the
        // argmax; scanning ascending makes the break exact.
        if (__ballot_sync(0xffffffffu, valid && (v == H))) break;
    }

    // Warp max-reduce of encoded best.
#pragma unroll
    for (int off = 16; off; off >>= 1)
        best = max(best, __shfl_xor_sync(0xffffffffu, best, off));

    int bv = best >> 11;
    int bk = 2047 - (best & 2047);
    float v0 = 0.0f, v1 = 0.0f;
    if (bv > 0) {
        v0 = g_values[bk * B + lane];
        v1 = g_values[bk * B + 32 + lane];
    }
    out[q * B + lane] = v0;
    out[q * B + 32 + lane] = v1;
}

// ---------------------------------------------------------------------------
extern "C" void kernel_launch(void* const* d_in, const int* in_sizes, int n_in,
                              void* d_out, int out_size) {
    const int*   tokens     = (const int*)d_in[0];
    const int*   conn_heads = (const int*)d_in[1];
    const float* head_table = (const float*)d_in[2];
    const int*   conn_v     = (const int*)d_in[3];
    const float* table_v    = (const float*)d_in[4];
    float* out = (float*)d_out;

    k_prep<<<(S * B) / 256, 256>>>(tokens, conn_heads, head_table, conn_v, table_v);
    k_main<<<S / 8, 256>>>(out);
}

// round 3
// speedup vs baseline: 1.6870x; 1.6870x over previous
#include <cuda_runtime.h>

#define S 2048
#define B 64
#define H 8
#define KK 12
#define NPOS 11
#define TBL 4096  // 1<<KK

// Scratch (__device__ globals; no allocations allowed).
__device__ uint4 g_AQ4[S];                 // per s: 8 x u16 = (h<<12) + addr_q (disjoint bits)
__device__ uint4 g_AK4[S];                 // per s: 8 x u16 = addr_k
__device__ uint4 g_AP4[S];                 // per rel: 8 x u16 = addr_p
__device__ uint4 g_tbw4[H * TBL / 32 / 4]; // bit table: word i, bit j = head_table[i*32+j]
__device__ float g_values[S * B];          // values[s][b] = table_v[b][addr_v(s,b)]

// ---------------------------------------------------------------------------
// Fused prep: bit table, per-(s,h) partial addresses, and values gather.
// Grid covers S*B = 131072 threads.
__global__ void __launch_bounds__(256) k_prep(
        const int* __restrict__ tokens,
        const int* __restrict__ conn_heads,
        const float* __restrict__ head_table,
        const int* __restrict__ conn_v,
        const float* __restrict__ table_v) {
    int i = blockIdx.x * blockDim.x + threadIdx.x;

    if (i < H * TBL / 32) {          // 1024 words
        unsigned w = 0;
#pragma unroll
        for (int j = 0; j < 32; j++)
            w |= (unsigned)(__ldg(&head_table[i * 32 + j]) != 0.0f) << j;
        ((unsigned*)g_tbw4)[i] = w;
    }

    if (i < S * H) {
        int s = i >> 3, h = i & 7;
        int aq = 0, ak = 0, ap = 0;
#pragma unroll
        for (int j = 0; j < KK; j++) {
            int c = __ldg(&conn_heads[h * KK + j]);
            int p2 = 1 << (KK - 1 - j);
            if (c < B)          aq += (__ldg(&tokens[s * B + c]) != 0) * p2;
            else if (c < 2 * B) ak += (__ldg(&tokens[s * B + (c - B)]) != 0) * p2;
            else                ap += ((s >> (NPOS - 1 - (c - 2 * B))) & 1) * p2;
        }
        ((unsigned short*)g_AQ4)[i] = (unsigned short)((h << 12) + aq);
        ((unsigned short*)g_AK4)[i] = (unsigned short)ak;
        ((unsigned short*)g_AP4)[i] = (unsigned short)ap;
    }

    {   // values: all S*B threads
        int s = i >> 6, b = i & 63;
        int addr = 0;
#pragma unroll
        for (int j = 0; j < KK; j++) {
            int c = __ldg(&conn_v[b * KK + j]);
            addr += (__ldg(&tokens[s * B + c]) != 0) << (KK - 1 - j);
        }
        g_values[i] = __ldg(&table_v[b * TBL + addr]);
    }
}

// ---------------------------------------------------------------------------
// Main: one block per query row q; 4KB bit table staged per block. Scan keys
// ascending in 256-wide chunks; single-barrier early exit via __syncthreads_or
// when any vote hits the maximum (H). Argmax with first-index tie-break via
// enc = (v<<11)|(2047-k).
__global__ void __launch_bounds__(256) k_main(float* __restrict__ out) {
    __shared__ unsigned s_tb[H * TBL / 32];   // 1024 words = 4 KB
    __shared__ int s_red[8];
    __shared__ int s_best;

    int tid = threadIdx.x;
    int q = blockIdx.x;

    ((uint4*)s_tb)[tid] = g_tbw4[tid];        // 256 uint4 = whole table
    uint4 aq = g_AQ4[q];
    __syncthreads();

    int best = -1;
    for (int c0 = 0; c0 <= q; c0 += 256) {
        int k = c0 + tid;
        int v = 0;
        bool valid = (k <= q);
        if (valid) {
            uint4 ak = __ldg(&g_AK4[k]);
            uint4 ap = __ldg(&g_AP4[q - k]);
            // packed u16 adds: (h<<12)+(aq+ak+ap) <= 32767 per lane, no carry.
            unsigned wx = ak.x + ap.x + aq.x;
            unsigned wy = ak.y + ap.y + aq.y;
            unsigned wz = ak.z + ap.z + aq.z;
            unsigned ww = ak.w + ap.w + aq.w;
            // bit lookup: word = addr16>>5 (h<<12 -> region h<<7), bit = addr16&31
            v  = (s_tb[(wx & 0xFFFFu) >> 5] >> (wx & 31)) & 1;
            v += (s_tb[wx >> 21] >> ((wx >> 16) & 31)) & 1;
            v += (s_tb[(wy & 0xFFFFu) >> 5] >> (wy & 31)) & 1;
            v += (s_tb[wy >> 21] >> ((wy >> 16) & 31)) & 1;
            v += (s_tb[(wz & 0xFFFFu) >> 5] >> (wz & 31)) & 1;
            v += (s_tb[wz >> 21] >> ((wz >> 16) & 31)) & 1;
            v += (s_tb[(ww & 0xFFFFu) >> 5] >> (ww & 31)) & 1;
            v += (s_tb[ww >> 21] >> ((ww >> 16) & 31)) & 1;
            best = max(best, (v << 11) | (2047 - k));
        }
        // Ascending scan: the first chunk containing the global-max vote (H)
        // holds the argmax; one fused barrier+OR per chunk.
        if (__syncthreads_or((int)(valid && v == H))) break;
    }

    // Block max-reduce of encoded best.
#pragma unroll
    for (int off = 16; off; off >>= 1)
        best = max(best, __shfl_xor_sync(0xffffffffu, best, off));
    if ((tid & 31) == 0) s_red[tid >> 5] = best;
    __syncthreads();
    if (tid == 0) {
        int m = s_red[0];
#pragma unroll
        for (int i = 1; i < 8; i++) m = max(m, s_red[i]);
        s_best = m;
    }
    __syncthreads();

    if (tid < B) {
        int m = s_best;
        int bv = m >> 11;
        int bk = 2047 - (m & 2047);
        out[q * B + tid] = (bv > 0) ? g_values[bk * B + tid] : 0.0f;
    }
}

// ---------------------------------------------------------------------------
extern "C" void kernel_launch(void* const* d_in, const int* in_sizes, int n_in,
                              void* d_out, int out_size) {
    const int*   tokens     = (const int*)d_in[0];
    const int*   conn_heads = (const int*)d_in[1];
    const float* head_table = (const float*)d_in[2];
    const int*   conn_v     = (const int*)d_in[3];
    const float* table_v    = (const float*)d_in[4];
    float* out = (float*)d_out;

    k_prep<<<(S * B) / 256, 256>>>(tokens, conn_heads, head_table, conn_v, table_v);
    k_main<<<S, 256>>>(out);
}

// round 4
// speedup vs baseline: 2.0968x; 1.2429x over previous
#include <cuda_runtime.h>

#define S 2048
#define B 64
#define H 8
#define KK 12
#define NPOS 11
#define TBL 4096  // 1<<KK

// Scratch (__device__ globals; no allocations allowed).
__device__ unsigned long long g_tokmask[S]; // 64 token bits per row
__device__ uint4 g_AQ4[S];                  // per s: 8 x u16 = (h<<12) + addr_q
__device__ uint4 g_AK4[S];                  // per s: 8 x u16 = addr_k
__device__ uint4 g_AP4[S];                  // per rel: 8 x u16 = addr_p
__device__ uint4 g_tbw4[H * TBL / 32 / 4];  // bit table: word i, bit j = head_table[i*32+j]

// ---------------------------------------------------------------------------
// Prep: one warp per row s (ballot mask; lanes 0..7 compute per-head partial
// addresses — the three groups partition the 12 bits, so aq+ak+ap <= 4095).
// First 1024 threads also build the bit table from float4 loads.
__global__ void __launch_bounds__(256) k_prep(
        const int* __restrict__ tokens,
        const int* __restrict__ conn_heads,
        const float* __restrict__ head_table) {
    int tid = threadIdx.x;
    int lane = tid & 31;
    int gw = blockIdx.x * 8 + (tid >> 5);    // row index, 0..2047

    int t0 = tokens[gw * B + lane];
    int t1 = tokens[gw * B + 32 + lane];
    unsigned lo = __ballot_sync(0xffffffffu, t0 != 0);
    unsigned hi = __ballot_sync(0xffffffffu, t1 != 0);
    unsigned long long tm = (unsigned long long)lo | ((unsigned long long)hi << 32);
    if (lane == 0) g_tokmask[gw] = tm;

    if (lane < H) {
        int h = lane;
        int aq = 0, ak = 0, ap = 0;
#pragma unroll
        for (int j = 0; j < KK; j++) {
            int c = __ldg(&conn_heads[h * KK + j]);
            int p2 = 1 << (KK - 1 - j);
            if (c < B)          aq += (int)((tm >> c) & 1ull) * p2;
            else if (c < 2 * B) ak += (int)((tm >> (c - B)) & 1ull) * p2;
            else                ap += ((gw >> (NPOS - 1 - (c - 2 * B))) & 1) * p2;
        }
        int i = gw * 8 + h;
        ((unsigned short*)g_AQ4)[i] = (unsigned short)((h << 12) + aq);
        ((unsigned short*)g_AK4)[i] = (unsigned short)ak;
        ((unsigned short*)g_AP4)[i] = (unsigned short)ap;
    }

    int i = blockIdx.x * 256 + tid;
    if (i < H * TBL / 32) {                  // 1024 table words
        const float4* ht4 = (const float4*)head_table;
        unsigned w = 0;
#pragma unroll
        for (int r = 0; r < 8; r++) {
            float4 f = __ldg(&ht4[i * 8 + r]);
            w |= (unsigned)(f.x != 0.0f) << (r * 4);
            w |= (unsigned)(f.y != 0.0f) << (r * 4 + 1);
            w |= (unsigned)(f.z != 0.0f) << (r * 4 + 2);
            w |= (unsigned)(f.w != 0.0f) << (r * 4 + 3);
        }
        ((unsigned*)g_tbw4)[i] = w;
    }
}

// ---------------------------------------------------------------------------
// Main: one block per query row q; 4KB bit table + conn_v staged per block.
// Ascending 256-wide chunk scan with prefetch; __syncthreads_or early exit
// when any vote hits the max (H). Tail computes the winning row's values
// directly from its token mask (no precomputed S*B values array).
__global__ void __launch_bounds__(256) k_main(
        const int* __restrict__ conn_v,
        const float* __restrict__ table_v,
        float* __restrict__ out) {
    __shared__ unsigned s_tb[H * TBL / 32];   // 1024 words = 4 KB
    __shared__ int s_conn[B * KK];            // 768 ints = 3 KB
    __shared__ int s_red[8];
    __shared__ int s_best;

    int tid = threadIdx.x;
    int q = blockIdx.x;

    // Issue all block-setup loads up front (overlap latencies).
    uint4 aq  = g_AQ4[q];
    uint4 tbw = g_tbw4[tid];
    int kc = min(tid, q);
    uint4 ak = __ldg(&g_AK4[kc]);
    uint4 ap = __ldg(&g_AP4[q - kc]);
    int c0 = __ldg(&conn_v[tid]);
    int c1 = __ldg(&conn_v[tid + 256]);
    int c2 = __ldg(&conn_v[tid + 512]);

    ((uint4*)s_tb)[tid] = tbw;
    s_conn[tid] = c0; s_conn[tid + 256] = c1; s_conn[tid + 512] = c2;
    __syncthreads();

    int best = -1;
    for (int base = 0; base <= q; base += 256) {
        int k = base + tid;
        bool valid = (k <= q);
        uint4 cak = ak, cap = ap;
        if (base + 256 <= q) {                // warp-uniform prefetch
            int kn = min(base + 256 + tid, q);
            ak = __ldg(&g_AK4[kn]);
            ap = __ldg(&g_AP4[q - kn]);
        }
        // packed u16 adds: (h<<12)+(aq+ak+ap) <= 32767 per lane, no carry.
        unsigned wx = cak.x + cap.x + aq.x;
        unsigned wy = cak.y + cap.y + aq.y;
        unsigned wz = cak.z + cap.z + aq.z;
        unsigned ww = cak.w + cap.w + aq.w;
        int v  = (s_tb[(wx & 0xFFFFu) >> 5] >> (wx & 31)) & 1;
        v += (s_tb[wx >> 21] >> ((wx >> 16) & 31)) & 1;
        v += (s_tb[(wy & 0xFFFFu) >> 5] >> (wy & 31)) & 1;
        v += (s_tb[wy >> 21] >> ((wy >> 16) & 31)) & 1;
        v += (s_tb[(wz & 0xFFFFu) >> 5] >> (wz & 31)) & 1;
        v += (s_tb[wz >> 21] >> ((wz >> 16) & 31)) & 1;
        v += (s_tb[(ww & 0xFFFFu) >> 5] >> (ww & 31)) & 1;
        v += (s_tb[ww >> 21] >> ((ww >> 16) & 31)) & 1;
        if (valid) best = max(best, (v << 11) | (2047 - k));
        // Ascending scan: first chunk containing the global-max vote (H)
        // holds the argmax; one fused barrier+OR per chunk.
        if (__syncthreads_or((int)(valid && v == H))) break;
    }

    // Block max-reduce of encoded best.
#pragma unroll
    for (int off = 16; off; off >>= 1)
        best = max(best, __shfl_xor_sync(0xffffffffu, best, off));
    if ((tid & 31) == 0) s_red[tid >> 5] = best;
    __syncthreads();
    if (tid == 0) {
        int m = s_red[0];
#pragma unroll
        for (int i = 1; i < 8; i++) m = max(m, s_red[i]);
        s_best = m;
    }
    __syncthreads();

    if (tid < B) {
        int m = s_best;
        int bv = m >> 11;
        int bk = 2047 - (m & 2047);
        float o = 0.0f;
        if (bv > 0) {
            unsigned long long msk = g_tokmask[bk];
            int addr = 0;
#pragma unroll
            for (int j = 0; j < KK; j++) {
                int c = s_conn[tid * KK + j];
                addr += (int)((msk >> c) & 1ull) << (KK - 1 - j);
            }
            o = __ldg(&table_v[tid * TBL + addr]);
        }
        out[q * B + tid] = o;
    }
}

// ---------------------------------------------------------------------------
extern "C" void kernel_launch(void* const* d_in, const int* in_sizes, int n_in,
                              void* d_out, int out_size) {
    const int*   tokens     = (const int*)d_in[0];
    const int*   conn_heads = (const int*)d_in[1];
    const float* head_table = (const float*)d_in[2];
    const int*   conn_v     = (const int*)d_in[3];
    const float* table_v    = (const float*)d_in[4];
    float* out = (float*)d_out;

    k_prep<<<S / 8, 256>>>(tokens, conn_heads, head_table);
    k_main<<<S, 256>>>(conn_v, table_v, out);
}